// round 14
// baseline (speedup 1.0000x reference)
#include <cuda_runtime.h>
#include <cuda_fp16.h>

#define HH 480
#define WW 640
#define HWP (HH*WW)          // 307200
#define BB 8
#define NEV 131072
#define SCALE 640.0f
#define EPSV 1e-9f

#define EPT 4                                  // events per splat thread
#define SPLAT_VB ((BB*NEV/EPT)/256)            // 1024
#define SMOOTH_VB ((BB*HWP + 255)/256)         // 9600
#define FUSED_VB (SPLAT_VB + SMOOTH_VB)        // 10624
#define LOSS_PX 4                              // pixels per loss thread
#define LOSS_GX ((HWP/LOSS_PX + 255)/256)      // 300
#define LOSS_VB (LOSS_GX * BB * 2)             // 4800

// fp16 accumulator: [b][dir][pixel][4 halves: pos_w, pos_ts, neg_w, neg_ts]
// 8 B/pixel, 39.3 MB total — L2-resident. Zero at init; loss restores zeros.
__device__ __align__(16) __half2 g_acc[BB * 2 * HWP * 2];

__device__ float g_sum[2][BB];
__device__ float g_nz[2][BB];
__device__ float g_sm[4];
__device__ unsigned g_barA = 0;   // phase-A arrival counter
__device__ unsigned g_done = 0;   // phase-B completion counter
__device__ unsigned g_vbA  = 0;   // phase-A work-stealing cursor
__device__ unsigned g_vbB  = 0;   // phase-B work-stealing cursor

__device__ __forceinline__ float warp_red(float v) {
    #pragma unroll
    for (int o = 16; o > 0; o >>= 1) v += __shfl_down_sync(0xffffffffu, v, o);
    return v;
}

__device__ __forceinline__ unsigned pack2(float a, float b) {
    __half2 h = __floats2half2_rn(a, b);
    return *reinterpret_cast<unsigned*>(&h);
}

__device__ __forceinline__ void red8(__half2* p, unsigned lo, unsigned hi) {
    asm volatile("red.global.add.noftz.v2.f16x2 [%0], {%1, %2};"
                 :: "l"(p), "r"(lo), "r"(hi) : "memory");
}
__device__ __forceinline__ void red16(__half2* p, unsigned a, unsigned b,
                                      unsigned c, unsigned d) {
    asm volatile("red.global.add.noftz.v4.f16x2 [%0], {%1, %2, %3, %4};"
                 :: "l"(p), "r"(a), "r"(b), "r"(c), "r"(d) : "memory");
}

__device__ __forceinline__ void row_taps(__half2* img, int iy, int lx,
                                         float wl, float wr, float tsw, bool pos) {
    if ((unsigned)iy >= (unsigned)HH) return;
    bool vl = (unsigned)lx < (unsigned)WW;
    bool vr = (unsigned)(lx + 1) < (unsigned)WW;
    unsigned pl = pack2(wl, wl * tsw);
    unsigned pr = pack2(wr, wr * tsw);
    unsigned l0 = pos ? pl : 0u, l1 = pos ? 0u : pl;
    unsigned r0 = pos ? pr : 0u, r1 = pos ? 0u : pr;
    size_t row = (size_t)iy * WW;
    if (((lx & 1) == 0) && vl && vr) {
        red16(img + ((row + lx) << 1), l0, l1, r0, r1);
    } else {
        if (vl) red8(img + ((row + lx)     << 1), l0, l1);
        if (vr) red8(img + ((row + lx + 1) << 1), r0, r1);
    }
}

__device__ __forceinline__ void splat_one(
        const __half2* imgs, int y, int x, float fxv, float fyv, float t0, bool pos) {
    float wy0 = (float)y + (1.0f - t0) * fyv;
    float wx0 = (float)x + (1.0f - t0) * fxv;
    float wy1 = wy0 - fyv;
    float wx1 = wx0 - fxv;
    #pragma unroll
    for (int dir = 0; dir < 2; dir++) {
        float wy  = (dir == 0) ? wy0 : wy1;
        float wx  = (dir == 0) ? wx0 : wx1;
        float tsw = (dir == 0) ? t0 : (1.0f - t0);

        float tyf = floorf(wy), lxf = floorf(wx);
        float ay = wy - tyf,    ax = wx - lxf;
        int ty = (int)tyf, lx = (int)lxf;

        float w00 = (1.0f - ay) * (1.0f - ax);
        float w01 = (1.0f - ay) * ax;
        float w10 = ay * (1.0f - ax);
        float w11 = ay * ax;

        __half2* img = (__half2*)imgs + ((size_t)(dir * HWP) << 1);
        row_taps(img, ty,     lx, w00, w01, tsw, pos);
        row_taps(img, ty + 1, lx, w10, w11, tsw, pos);
    }
}

// EPT events per thread; vectorized event loads.
__device__ __forceinline__ void splat_work(
        int blk,
        const float* __restrict__ flow, const float* __restrict__ ts,
        const int* __restrict__ ys, const int* __restrict__ xs,
        const int* __restrict__ pol) {
    int t = blk * 256 + threadIdx.x;          // event-quad index
    int b = (t * EPT) >> 17;                  // all EPT events same batch
    int4   yy = __ldg((const int4*)ys + t);
    int4   xx = __ldg((const int4*)xs + t);
    int4   pp = __ldg((const int4*)pol + t);
    float4 tt = __ldg((const float4*)ts + t);

    const float* fb = flow + (size_t)b * 2 * HWP;
    int f0 = yy.x * WW + xx.x;
    int f1 = yy.y * WW + xx.y;
    int f2 = yy.z * WW + xx.z;
    int f3 = yy.w * WW + xx.w;
    float fx0 = __ldg(fb + f0), fy0 = __ldg(fb + HWP + f0);
    float fx1 = __ldg(fb + f1), fy1 = __ldg(fb + HWP + f1);
    float fx2 = __ldg(fb + f2), fy2 = __ldg(fb + HWP + f2);
    float fx3 = __ldg(fb + f3), fy3 = __ldg(fb + HWP + f3);

    const __half2* imgs = g_acc + ((size_t)(b * 2 * HWP) << 1);
    splat_one(imgs, yy.x, xx.x, fx0 * SCALE, fy0 * SCALE, tt.x, pp.x != 0);
    splat_one(imgs, yy.y, xx.y, fx1 * SCALE, fy1 * SCALE, tt.y, pp.y != 0);
    splat_one(imgs, yy.z, xx.z, fx2 * SCALE, fy2 * SCALE, tt.z, pp.z != 0);
    splat_one(imgs, yy.w, xx.w, fx3 * SCALE, fy3 * SCALE, tt.w, pp.w != 0);
}

__device__ __forceinline__ float charb(float a, float b) {
    float x = fmaf(a, a, fmaf(b, b, 1e-6f));
    return x * rsqrtf(x);
}

__device__ __forceinline__ void smooth_work(int blk, const float* __restrict__ flow,
                                            float sm[4][8]) {
    int t = blk * 256 + threadIdx.x;
    float s0 = 0.f, s1 = 0.f, s2 = 0.f, s3 = 0.f;
    if (t < BB * HWP) {
        int b = t / HWP;
        int pix = t - b * HWP;
        int y = pix / WW;
        int x = pix - y * WW;
        const float* fx = flow + (size_t)b * 2 * HWP;
        const float* fy = fx + HWP;
        float fx00 = fx[pix], fy00 = fy[pix];
        bool xr = (x < WW - 1), yd = (y < HH - 1);
        float fx01 = 0.f, fy01 = 0.f, fx10 = 0.f, fy10 = 0.f, fx11 = 0.f, fy11 = 0.f;
        if (xr)       { fx01 = fx[pix + 1];      fy01 = fy[pix + 1]; }
        if (yd)       { fx10 = fx[pix + WW];     fy10 = fy[pix + WW]; }
        if (xr && yd) { fx11 = fx[pix + WW + 1]; fy11 = fy[pix + WW + 1]; }
        if (xr) s0 = charb(fx00 - fx01, fy00 - fy01);
        if (yd) s1 = charb(fx00 - fx10, fy00 - fy10);
        if (xr && yd) {
            s2 = charb(fx00 - fx11, fy00 - fy11);
            s3 = charb(fx10 - fx01, fy10 - fy01);
        }
    }
    int lane = threadIdx.x & 31, warp = threadIdx.x >> 5;
    s0 = warp_red(s0); s1 = warp_red(s1); s2 = warp_red(s2); s3 = warp_red(s3);
    if (lane == 0) { sm[0][warp] = s0; sm[1][warp] = s1; sm[2][warp] = s2; sm[3][warp] = s3; }
    __syncthreads();
    if (threadIdx.x == 0) {
        float a0 = 0.f, a1 = 0.f, a2 = 0.f, a3 = 0.f;
        #pragma unroll
        for (int i = 0; i < 8; i++) { a0 += sm[0][i]; a1 += sm[1][i]; a2 += sm[2][i]; a3 += sm[3][i]; }
        atomicAdd(&g_sm[0], a0);
        atomicAdd(&g_sm[1], a1);
        atomicAdd(&g_sm[2], a2);
        atomicAdd(&g_sm[3], a3);
    }
    __syncthreads();
}

__device__ __forceinline__ void loss_work(int vb, float sm[4][8]) {
    int img = vb / LOSS_GX;               // b*2 + dir
    int s   = (vb - img * LOSS_GX) * 256 + threadIdx.x;   // quad-pixel slot
    int b   = img >> 1;
    int dir = img & 1;
    float v0 = 0.f, v1 = 0.f;
    if (s < HWP / LOSS_PX) {
        uint4* a = (uint4*)(g_acc + ((size_t)img * HWP + (size_t)s * LOSS_PX) * 2);
        #pragma unroll
        for (int q = 0; q < LOSS_PX / 2; q++) {
            uint4 v = a[q];
            a[q] = make_uint4(0u, 0u, 0u, 0u);
            #pragma unroll
            for (int k = 0; k < 2; k++) {
                unsigned up = k ? v.z : v.x;
                unsigned un = k ? v.w : v.y;
                __half2 hp = *reinterpret_cast<__half2*>(&up);
                __half2 hn = *reinterpret_cast<__half2*>(&un);
                float pw  = __low2float(hp),  pts = __high2float(hp);
                float nw  = __low2float(hn),  nts = __high2float(hn);
                float r0 = pts / (pw + EPSV);
                float r1 = nts / (nw + EPSV);
                v0 += r0 * r0 + r1 * r1;
                v1 += (pw + nw > 0.0f) ? 1.0f : 0.0f;
            }
        }
    }
    int lane = threadIdx.x & 31, warp = threadIdx.x >> 5;
    v0 = warp_red(v0); v1 = warp_red(v1);
    if (lane == 0) { sm[0][warp] = v0; sm[1][warp] = v1; }
    __syncthreads();
    if (threadIdx.x == 0) {
        float a0 = 0.f, a1 = 0.f;
        #pragma unroll
        for (int i = 0; i < 8; i++) { a0 += sm[0][i]; a1 += sm[1][i]; }
        atomicAdd(&g_sum[dir][b], a0);
        atomicAdd(&g_nz[dir][b],  a1);
    }
    __syncthreads();
}

// Persistent kernel with dynamic work stealing in both phases.
__global__ void __launch_bounds__(256, 8) persist_kernel(
        const float* __restrict__ flow, const float* __restrict__ ts,
        const int* __restrict__ ys, const int* __restrict__ xs,
        const int* __restrict__ pol, float* out, int n) {
    __shared__ float sm[4][8];
    __shared__ unsigned s_vb;
    int grid = gridDim.x;

    // ---- Phase A: splat + smooth, interleaved order, stolen dynamically ----
    for (;;) {
        if (threadIdx.x == 0) s_vb = atomicAdd(&g_vbA, 1u);
        __syncthreads();
        unsigned vb = s_vb;
        if (vb >= FUSED_VB) break;
        long long sb  = ((long long)vb * SPLAT_VB) / FUSED_VB;
        long long sb1 = ((long long)(vb + 1) * SPLAT_VB) / FUSED_VB;
        if (sb1 > sb) {
            splat_work((int)sb, flow, ts, ys, xs, pol);
            __syncthreads();
        } else {
            smooth_work((int)(vb - sb), flow, sm);
        }
    }

    // ---- Device-wide barrier ----
    if (threadIdx.x == 0) {
        __threadfence();
        atomicAdd(&g_barA, 1u);
        while (*(volatile unsigned*)&g_barA < (unsigned)grid) __nanosleep(200);
    }
    __syncthreads();
    __threadfence();

    // ---- Phase B: per-pixel loss, stolen dynamically ----
    for (;;) {
        if (threadIdx.x == 0) s_vb = atomicAdd(&g_vbB, 1u);
        __syncthreads();
        unsigned vb = s_vb;
        if (vb >= LOSS_VB) break;
        loss_work((int)vb, sm);
    }

    // ---- Final: last block reduces to the scalar and resets state ----
    if (threadIdx.x == 0) {
        __threadfence();
        unsigned done = atomicAdd(&g_done, 1u);
        if (done == (unsigned)grid - 1u) {
            float loss = 0.0f;
            #pragma unroll
            for (int bb = 0; bb < BB; bb++) {
                loss += g_sum[0][bb] / g_nz[0][bb];
                loss += g_sum[1][bb] / g_nz[1][bb];
            }
            float mdx = g_sm[0] / (float)(BB * HH * (WW - 1));
            float mdy = g_sm[1] / (float)(BB * (HH - 1) * WW);
            float mdr = g_sm[2] / (float)(BB * (HH - 1) * (WW - 1));
            float mur = g_sm[3] / (float)(BB * (HH - 1) * (WW - 1));
            loss += 0.001f * 0.25f * (mdx + mdy + mdr + mur);
            for (int i = 0; i < n; i++) out[i] = loss;
            #pragma unroll
            for (int bb = 0; bb < BB; bb++) {
                g_sum[0][bb] = 0.f; g_sum[1][bb] = 0.f;
                g_nz[0][bb]  = 0.f; g_nz[1][bb]  = 0.f;
            }
            #pragma unroll
            for (int i = 0; i < 4; i++) g_sm[i] = 0.f;
            g_barA = 0; g_done = 0; g_vbA = 0; g_vbB = 0;
        }
    }
}

extern "C" void kernel_launch(void* const* d_in, const int* in_sizes, int n_in,
                              void* d_out, int out_size) {
    const float* flow = (const float*)d_in[0];
    const float* ts   = (const float*)d_in[1];
    const int*   ys   = (const int*)d_in[2];
    const int*   xs   = (const int*)d_in[3];
    const int*   pol  = (const int*)d_in[4];

    int dev = 0, sms = 0, maxb = 0;
    cudaGetDevice(&dev);
    cudaDeviceGetAttribute(&sms, cudaDevAttrMultiProcessorCount, dev);
    cudaOccupancyMaxActiveBlocksPerMultiprocessor(&maxb, persist_kernel, 256, 0);
    int grid = sms * maxb;                       // all blocks resident: barrier-safe
    if (grid > FUSED_VB) grid = FUSED_VB;

    persist_kernel<<<grid, 256>>>(flow, ts, ys, xs, pol, (float*)d_out, out_size);
}

// round 15
// speedup vs baseline: 1.5574x; 1.5574x over previous
#include <cuda_runtime.h>
#include <cuda_fp16.h>

#define HH 480
#define WW 640
#define HWP (HH*WW)          // 307200
#define BB 8
#define NEV 131072
#define SCALE 640.0f
#define EPSV 1e-9f

#define SPLAT_VB ((BB*NEV/2)/256)              // 2048 (2 events/thread)
#define SMOOTH_VB ((BB*HWP + 255)/256)         // 9600
#define FUSED_VB (SPLAT_VB + SMOOTH_VB)        // 11648
#define LOSS_GX ((HWP/2 + 255)/256)            // 300
#define LOSS_VB (LOSS_GX * BB * 2)             // 4800

// fp16 accumulator: [b][dir][pixel][4 halves: pos_w, pos_ts, neg_w, neg_ts]
// 8 B/pixel, 39.3 MB total — L2-resident. Zero at init; loss restores zeros.
__device__ __align__(16) __half2 g_acc[BB * 2 * HWP * 2];

__device__ float g_sum[2][BB];
__device__ float g_nz[2][BB];
__device__ float g_sm[4];
__device__ unsigned g_barA = 0;   // phase-A arrival counter
__device__ unsigned g_done = 0;   // phase-B completion counter

__device__ __forceinline__ float warp_red(float v) {
    #pragma unroll
    for (int o = 16; o > 0; o >>= 1) v += __shfl_down_sync(0xffffffffu, v, o);
    return v;
}

__device__ __forceinline__ unsigned pack2(float a, float b) {
    __half2 h = __floats2half2_rn(a, b);
    return *reinterpret_cast<unsigned*>(&h);
}

__device__ __forceinline__ void red8(__half2* p, unsigned lo, unsigned hi) {
    asm volatile("red.global.add.noftz.v2.f16x2 [%0], {%1, %2};"
                 :: "l"(p), "r"(lo), "r"(hi) : "memory");
}
__device__ __forceinline__ void red16(__half2* p, unsigned a, unsigned b,
                                      unsigned c, unsigned d) {
    asm volatile("red.global.add.noftz.v4.f16x2 [%0], {%1, %2, %3, %4};"
                 :: "l"(p), "r"(a), "r"(b), "r"(c), "r"(d) : "memory");
}

__device__ __forceinline__ void row_taps(__half2* img, int iy, int lx,
                                         float wl, float wr, float tsw, bool pos) {
    if ((unsigned)iy >= (unsigned)HH) return;
    bool vl = (unsigned)lx < (unsigned)WW;
    bool vr = (unsigned)(lx + 1) < (unsigned)WW;
    unsigned pl = pack2(wl, wl * tsw);
    unsigned pr = pack2(wr, wr * tsw);
    unsigned l0 = pos ? pl : 0u, l1 = pos ? 0u : pl;
    unsigned r0 = pos ? pr : 0u, r1 = pos ? 0u : pr;
    size_t row = (size_t)iy * WW;
    if (((lx & 1) == 0) && vl && vr) {
        red16(img + ((row + lx) << 1), l0, l1, r0, r1);
    } else {
        if (vl) red8(img + ((row + lx)     << 1), l0, l1);
        if (vr) red8(img + ((row + lx + 1) << 1), r0, r1);
    }
}

__device__ __forceinline__ void splat_one(
        int b, int y, int x, float fxv, float fyv, float t0, bool pos) {
    float wy0 = (float)y + (1.0f - t0) * fyv;
    float wx0 = (float)x + (1.0f - t0) * fxv;
    float wy1 = wy0 - fyv;
    float wx1 = wx0 - fxv;
    #pragma unroll
    for (int dir = 0; dir < 2; dir++) {
        float wy  = (dir == 0) ? wy0 : wy1;
        float wx  = (dir == 0) ? wx0 : wx1;
        float tsw = (dir == 0) ? t0 : (1.0f - t0);

        float tyf = floorf(wy), lxf = floorf(wx);
        float ay = wy - tyf,    ax = wx - lxf;
        int ty = (int)tyf, lx = (int)lxf;

        float w00 = (1.0f - ay) * (1.0f - ax);
        float w01 = (1.0f - ay) * ax;
        float w10 = ay * (1.0f - ax);
        float w11 = ay * ax;

        __half2* img = g_acc + ((size_t)((b * 2 + dir) * HWP) << 1);
        row_taps(img, ty,     lx, w00, w01, tsw, pos);
        row_taps(img, ty + 1, lx, w10, w11, tsw, pos);
    }
}

__device__ __forceinline__ void splat_work(
        int blk,
        const float* __restrict__ flow, const float* __restrict__ ts,
        const int* __restrict__ ys, const int* __restrict__ xs,
        const int* __restrict__ pol) {
    int t = blk * 256 + threadIdx.x;          // event-pair index
    int b = (t * 2) >> 17;                    // both events same batch (NEV even)
    int2   yy = __ldg((const int2*)ys + t);
    int2   xx = __ldg((const int2*)xs + t);
    int2   pp = __ldg((const int2*)pol + t);
    float2 tt = __ldg((const float2*)ts + t);

    const float* fb = flow + (size_t)b * 2 * HWP;
    int flat0 = yy.x * WW + xx.x;
    int flat1 = yy.y * WW + xx.y;
    float fx0 = __ldg(fb + flat0) * SCALE;
    float fx1 = __ldg(fb + flat1) * SCALE;
    float fy0 = __ldg(fb + HWP + flat0) * SCALE;
    float fy1 = __ldg(fb + HWP + flat1) * SCALE;

    splat_one(b, yy.x, xx.x, fx0, fy0, tt.x, pp.x != 0);
    splat_one(b, yy.y, xx.y, fx1, fy1, tt.y, pp.y != 0);
}

// Charbonnier via one MUFU: sqrt(x) = x * rsqrt(x), x >= 1e-6 so safe.
__device__ __forceinline__ float charb(float a, float b) {
    float x = fmaf(a, a, fmaf(b, b, 1e-6f));
    return x * rsqrtf(x);
}

// Accumulates into caller registers; NO sync, NO atomics per VB.
__device__ __forceinline__ void smooth_work(int blk, const float* __restrict__ flow,
                                            float& s0, float& s1, float& s2, float& s3) {
    int t = blk * 256 + threadIdx.x;
    if (t >= BB * HWP) return;
    int b = t / HWP;
    int pix = t - b * HWP;
    int y = pix / WW;
    int x = pix - y * WW;
    const float* fx = flow + (size_t)b * 2 * HWP;
    const float* fy = fx + HWP;
    float fx00 = fx[pix], fy00 = fy[pix];
    bool xr = (x < WW - 1), yd = (y < HH - 1);
    float fx01 = 0.f, fy01 = 0.f, fx10 = 0.f, fy10 = 0.f, fx11 = 0.f, fy11 = 0.f;
    if (xr)       { fx01 = fx[pix + 1];      fy01 = fy[pix + 1]; }
    if (yd)       { fx10 = fx[pix + WW];     fy10 = fy[pix + WW]; }
    if (xr && yd) { fx11 = fx[pix + WW + 1]; fy11 = fy[pix + WW + 1]; }
    if (xr) s0 += charb(fx00 - fx01, fy00 - fy01);
    if (yd) s1 += charb(fx00 - fx10, fy00 - fy10);
    if (xr && yd) {
        s2 += charb(fx00 - fx11, fy00 - fy11);
        s3 += charb(fx10 - fx01, fy10 - fy01);
    }
}

__device__ __forceinline__ void loss_work(int vb, float sm[4][8]) {
    int img = vb / LOSS_GX;               // b*2 + dir
    int s   = (vb - img * LOSS_GX) * 256 + threadIdx.x;
    int b   = img >> 1;
    int dir = img & 1;
    float v0 = 0.f, v1 = 0.f;
    if (s < HWP / 2) {
        uint4* a = (uint4*)(g_acc + ((size_t)img * HWP + (size_t)s * 2) * 2);
        uint4 v = *a;
        *a = make_uint4(0u, 0u, 0u, 0u);
        #pragma unroll
        for (int k = 0; k < 2; k++) {
            unsigned up = k ? v.z : v.x;
            unsigned un = k ? v.w : v.y;
            __half2 hp = *reinterpret_cast<__half2*>(&up);
            __half2 hn = *reinterpret_cast<__half2*>(&un);
            float pw  = __low2float(hp),  pts = __high2float(hp);
            float nw  = __low2float(hn),  nts = __high2float(hn);
            float r0 = pts / (pw + EPSV);
            float r1 = nts / (nw + EPSV);
            v0 += r0 * r0 + r1 * r1;
            v1 += (pw + nw > 0.0f) ? 1.0f : 0.0f;
        }
    }
    int lane = threadIdx.x & 31, warp = threadIdx.x >> 5;
    v0 = warp_red(v0); v1 = warp_red(v1);
    if (lane == 0) { sm[0][warp] = v0; sm[1][warp] = v1; }
    __syncthreads();
    if (threadIdx.x == 0) {
        float a0 = 0.f, a1 = 0.f;
        #pragma unroll
        for (int i = 0; i < 8; i++) { a0 += sm[0][i]; a1 += sm[1][i]; }
        atomicAdd(&g_sum[dir][b], a0);
        atomicAdd(&g_nz[dir][b],  a1);
    }
    __syncthreads();
}

// Persistent kernel: phase A (splat+smooth interleaved, static strided map,
// smooth reduced ONCE at phase end) -> device barrier -> phase B (loss) ->
// last block computes the final scalar + resets state.
__global__ void __launch_bounds__(256, 8) persist_kernel(
        const float* __restrict__ flow, const float* __restrict__ ts,
        const int* __restrict__ ys, const int* __restrict__ xs,
        const int* __restrict__ pol, float* out, int n) {
    __shared__ float sm[4][8];
    int grid = gridDim.x;

    // ---- Phase A: splat + smooth (Bresenham-interleaved virtual blocks) ----
    float s0 = 0.f, s1 = 0.f, s2 = 0.f, s3 = 0.f;
    for (int vb = blockIdx.x; vb < FUSED_VB; vb += grid) {
        long long sb  = ((long long)vb * SPLAT_VB) / FUSED_VB;
        long long sb1 = ((long long)(vb + 1) * SPLAT_VB) / FUSED_VB;
        if (sb1 > sb) {
            splat_work((int)sb, flow, ts, ys, xs, pol);
        } else {
            smooth_work(vb - (int)sb, flow, s0, s1, s2, s3);
        }
    }
    // single smooth reduction per block
    {
        int lane = threadIdx.x & 31, warp = threadIdx.x >> 5;
        s0 = warp_red(s0); s1 = warp_red(s1); s2 = warp_red(s2); s3 = warp_red(s3);
        if (lane == 0) { sm[0][warp] = s0; sm[1][warp] = s1; sm[2][warp] = s2; sm[3][warp] = s3; }
        __syncthreads();
        if (threadIdx.x == 0) {
            float a0 = 0.f, a1 = 0.f, a2 = 0.f, a3 = 0.f;
            #pragma unroll
            for (int i = 0; i < 8; i++) { a0 += sm[0][i]; a1 += sm[1][i]; a2 += sm[2][i]; a3 += sm[3][i]; }
            atomicAdd(&g_sm[0], a0);
            atomicAdd(&g_sm[1], a1);
            atomicAdd(&g_sm[2], a2);
            atomicAdd(&g_sm[3], a3);
        }
    }

    // ---- Device-wide barrier ----
    __syncthreads();
    if (threadIdx.x == 0) {
        __threadfence();
        atomicAdd(&g_barA, 1u);
        while (*(volatile unsigned*)&g_barA < (unsigned)grid) __nanosleep(200);
    }
    __syncthreads();
    __threadfence();

    // ---- Phase B: per-pixel loss ----
    for (int vb = blockIdx.x; vb < LOSS_VB; vb += grid) {
        loss_work(vb, sm);
    }

    // ---- Final: last block reduces to the scalar and resets state ----
    __syncthreads();
    if (threadIdx.x == 0) {
        __threadfence();
        unsigned done = atomicAdd(&g_done, 1u);
        if (done == (unsigned)grid - 1u) {
            float loss = 0.0f;
            #pragma unroll
            for (int bb = 0; bb < BB; bb++) {
                loss += g_sum[0][bb] / g_nz[0][bb];
                loss += g_sum[1][bb] / g_nz[1][bb];
            }
            float mdx = g_sm[0] / (float)(BB * HH * (WW - 1));
            float mdy = g_sm[1] / (float)(BB * (HH - 1) * WW);
            float mdr = g_sm[2] / (float)(BB * (HH - 1) * (WW - 1));
            float mur = g_sm[3] / (float)(BB * (HH - 1) * (WW - 1));
            loss += 0.001f * 0.25f * (mdx + mdy + mdr + mur);
            for (int i = 0; i < n; i++) out[i] = loss;
            #pragma unroll
            for (int bb = 0; bb < BB; bb++) {
                g_sum[0][bb] = 0.f; g_sum[1][bb] = 0.f;
                g_nz[0][bb]  = 0.f; g_nz[1][bb]  = 0.f;
            }
            #pragma unroll
            for (int i = 0; i < 4; i++) g_sm[i] = 0.f;
            g_barA = 0; g_done = 0;
        }
    }
}

extern "C" void kernel_launch(void* const* d_in, const int* in_sizes, int n_in,
                              void* d_out, int out_size) {
    const float* flow = (const float*)d_in[0];
    const float* ts   = (const float*)d_in[1];
    const int*   ys   = (const int*)d_in[2];
    const int*   xs   = (const int*)d_in[3];
    const int*   pol  = (const int*)d_in[4];

    int dev = 0, sms = 0, maxb = 0;
    cudaGetDevice(&dev);
    cudaDeviceGetAttribute(&sms, cudaDevAttrMultiProcessorCount, dev);
    cudaOccupancyMaxActiveBlocksPerMultiprocessor(&maxb, persist_kernel, 256, 0);
    int grid = sms * maxb;                       // all blocks resident: barrier-safe
    if (grid > FUSED_VB) grid = FUSED_VB;

    persist_kernel<<<grid, 256>>>(flow, ts, ys, xs, pol, (float*)d_out, out_size);
}